// round 14
// baseline (speedup 1.0000x reference)
#include <cuda_runtime.h>
#include <cstdint>
#include <math_constants.h>

#define TOKENS   32768
#define DIM      2048
#define NE       64
#define TOPK     6

#define BM       128              // tokens per CTA
#define BKT      32               // K per chunk
#define NCHUNK   (DIM / BKT)      // 64
#define THREADS  512              // 16 warps: 4 across M (32 rows), 4 across N (16 cols)

#define KB2      40               // bf16 row stride (elements): 32 + 8 pad -> conflict-free frags
#define ROWB     (KB2 * 2)        // 80 bytes per row

#define OFF_AH   0
#define OFF_AM   (BM * ROWB)                       // 10240
#define OFF_WH   (2 * BM * ROWB)                   // 20480
#define OFF_WM   (2 * BM * ROWB + NE * ROWB)       // 25600
#define STAGE_B  (2 * BM * ROWB + 2 * NE * ROWB)   // 30720
#define BIAS_OFF (2 * STAGE_B)
#define SMEM_BYTES (BIAS_OFF + 256)

#define LSTR     66               // epilogue logits row stride (floats)
#define FLAG_GAP 4e-6f            // ~8x above 4-term bf16 score noise (~5e-7)

// ---- flat flagged-token list ----
__device__ int g_nflag;
__device__ int g_flags[TOKENS];

// pack two fp32 -> bf16x2, round-to-nearest
__device__ __forceinline__ uint32_t pack_bf16(float hi, float lo) {
    uint32_t d;
    asm("cvt.rn.bf16x2.f32 %0, %1, %2;" : "=r"(d) : "f"(hi), "f"(lo));
    return d;
}
__device__ __forceinline__ float bf_lo(uint32_t p) { return __uint_as_float(p << 16); }
__device__ __forceinline__ float bf_hi(uint32_t p) { return __uint_as_float(p & 0xFFFF0000u); }

struct Duo { uint2 h, m; };
// 2-way bf16 split of 4 consecutive values: v ~= h + m (residual ~2^-18 rel)
__device__ __forceinline__ Duo split4(float4 v) {
    Duo t;
    t.h.x = pack_bf16(v.y, v.x);
    t.h.y = pack_bf16(v.w, v.z);
    float r0 = v.x - bf_lo(t.h.x), r1 = v.y - bf_hi(t.h.x);
    float r2 = v.z - bf_lo(t.h.y), r3 = v.w - bf_hi(t.h.y);
    t.m.x = pack_bf16(r1, r0);
    t.m.y = pack_bf16(r3, r2);
    return t;
}

// m16n8k16 bf16 mma, f32 accumulate in-place
__device__ __forceinline__ void mma16(float* c, const uint32_t* a, uint32_t b0, uint32_t b1) {
    asm volatile(
        "mma.sync.aligned.m16n8k16.row.col.f32.bf16.bf16.f32 "
        "{%0,%1,%2,%3}, {%4,%5,%6,%7}, {%8,%9}, {%0,%1,%2,%3};"
        : "+f"(c[0]), "+f"(c[1]), "+f"(c[2]), "+f"(c[3])
        : "r"(a[0]), "r"(a[1]), "r"(a[2]), "r"(a[3]), "r"(b0), "r"(b1));
}

// ============================ PASS 1: bf16 4-term MMA GEMM + gate ============================
__global__ __launch_bounds__(THREADS, 2)
void gate_kernel(const float* __restrict__ x,
                 const float* __restrict__ w,
                 const float* __restrict__ bias,
                 float* __restrict__ out)
{
    extern __shared__ __align__(16) unsigned char smem[];
    float* sBias = reinterpret_cast<float*>(smem + BIAS_OFF);
    float* sLog  = reinterpret_cast<float*>(smem);   // epilogue overlay

    const int tid  = threadIdx.x;
    const int lane = tid & 31;
    const int wid  = tid >> 5;          // 0..15
    const int gid  = lane >> 2;
    const int tg   = lane & 3;
    const int m0   = (wid & 3) * 32;    // 4 M-warps x 32 rows
    const int n0   = (wid >> 2) * 16;   // 4 N-warps x 16 cols
    const int block_m = blockIdx.x * BM;

    if (tid < NE) sBias[tid] = bias[tid];

    const float* xg = x + (size_t)block_m * DIM;

    float acc[2][2][4];
    #pragma unroll
    for (int mt = 0; mt < 2; mt++)
        #pragma unroll
        for (int nt = 0; nt < 2; nt++)
            #pragma unroll
            for (int r = 0; r < 4; r++) acc[mt][nt][r] = 0.f;

    // LDG tiling per chunk: A 4096 floats -> 2 float4/thread; W 2048 -> 1 float4/thread
    float4 xr[2], wr;
    int xtok[2], xcq[2];
    #pragma unroll
    for (int i = 0; i < 2; i++) {
        int li = i * THREADS + tid; xtok[i] = li >> 3; xcq[i] = li & 7;
    }
    const int wexp = tid >> 3, wcq = tid & 7;

    auto ldg_chunk = [&](int c) {
        int k0 = c * BKT;
        #pragma unroll
        for (int i = 0; i < 2; i++)
            xr[i] = *reinterpret_cast<const float4*>(xg + (size_t)xtok[i] * DIM + k0 + xcq[i] * 4);
        wr = *reinterpret_cast<const float4*>(w + (size_t)wexp * DIM + k0 + wcq * 4);
    };
    auto sts_chunk = [&](int s) {
        unsigned char* st = smem + s * STAGE_B;
        #pragma unroll
        for (int i = 0; i < 2; i++) {
            Duo t = split4(xr[i]);
            int off = xtok[i] * ROWB + xcq[i] * 8;
            *reinterpret_cast<uint2*>(st + OFF_AH + off) = t.h;
            *reinterpret_cast<uint2*>(st + OFF_AM + off) = t.m;
        }
        {
            Duo t = split4(wr);
            int off = wexp * ROWB + wcq * 8;
            *reinterpret_cast<uint2*>(st + OFF_WH + off) = t.h;
            *reinterpret_cast<uint2*>(st + OFF_WM + off) = t.m;
        }
    };

    ldg_chunk(0);
    sts_chunk(0);
    __syncthreads();
    ldg_chunk(1);

    for (int c = 0; c < NCHUNK; c++) {
        const int s = c & 1;
        if (c + 1 < NCHUNK) {
            sts_chunk(s ^ 1);
            if (c + 2 < NCHUNK) ldg_chunk(c + 2);
        }

        const unsigned char* st = smem + s * STAGE_B;
        const uint32_t* Ah = reinterpret_cast<const uint32_t*>(st + OFF_AH);
        const uint32_t* Am = reinterpret_cast<const uint32_t*>(st + OFF_AM);
        const uint32_t* Wh = reinterpret_cast<const uint32_t*>(st + OFF_WH);
        const uint32_t* Wm = reinterpret_cast<const uint32_t*>(st + OFF_WM);

        #pragma unroll
        for (int q = 0; q < BKT / 16; q++) {
            const int kw = q * 8 + tg;

            uint32_t ah[2][4], am[2][4];
            #pragma unroll
            for (int mt = 0; mt < 2; mt++) {
                int r0 = (m0 + mt * 16 + gid) * (ROWB / 4);
                int r1 = r0 + 8 * (ROWB / 4);
                ah[mt][0] = Ah[r0 + kw];     ah[mt][1] = Ah[r1 + kw];
                ah[mt][2] = Ah[r0 + kw + 4]; ah[mt][3] = Ah[r1 + kw + 4];
                am[mt][0] = Am[r0 + kw];     am[mt][1] = Am[r1 + kw];
                am[mt][2] = Am[r0 + kw + 4]; am[mt][3] = Am[r1 + kw + 4];
            }

            #pragma unroll
            for (int nt = 0; nt < 2; nt++) {
                int rn = (n0 + nt * 8 + gid) * (ROWB / 4);
                uint32_t bh0 = Wh[rn + kw], bh1 = Wh[rn + kw + 4];
                uint32_t bm0 = Wm[rn + kw], bm1 = Wm[rn + kw + 4];
                #pragma unroll
                for (int mt = 0; mt < 2; mt++) {
                    float* cc = acc[mt][nt];
                    mma16(cc, ah[mt], bh0, bh1);   // hi*hi
                    mma16(cc, ah[mt], bm0, bm1);   // hi*mid
                    mma16(cc, am[mt], bh0, bh1);   // mid*hi
                    mma16(cc, am[mt], bm0, bm1);   // mid*mid
                }
            }
        }
        __syncthreads();
    }

    // ---- dump logits ----
    #pragma unroll
    for (int mt = 0; mt < 2; mt++)
        #pragma unroll
        for (int nt = 0; nt < 2; nt++) {
            int row = m0 + mt * 16 + gid;
            int col = n0 + nt * 8 + tg * 2;
            *reinterpret_cast<float2*>(&sLog[row * LSTR + col]) =
                make_float2(acc[mt][nt][0], acc[mt][nt][1]);
            *reinterpret_cast<float2*>(&sLog[(row + 8) * LSTR + col]) =
                make_float2(acc[mt][nt][2], acc[mt][nt][3]);
        }
    __syncthreads();

    // ---- epilogue: softmax, top-6, ambiguity flag ----
    if (tid < BM) {
        float* row = sLog + tid * LSTR;

        float m = row[0];
        #pragma unroll
        for (int e = 1; e < NE; e++) m = fmaxf(m, row[e]);
        float ssum = 0.f;
        #pragma unroll
        for (int e = 0; e < NE; e++) { float ex = __expf(row[e] - m); row[e] = ex; ssum += ex; }
        float inv = 1.0f / ssum;
        #pragma unroll
        for (int e = 0; e < NE; e++) row[e] *= inv;

        const int t = block_m + tid;
        float* outw = out + (size_t)t * TOPK;
        float* outi = out + (size_t)TOKENS * TOPK + (size_t)t * TOPK;

        float prev = 0.f, minGap = CUDART_INF_F;
        #pragma unroll
        for (int k = 0; k < TOPK + 1; k++) {
            float best = -CUDART_INF_F; int bi = 0;
            #pragma unroll
            for (int e = 0; e < NE; e++) {
                float b = row[e] + sBias[e];
                if (b > best) { best = b; bi = e; }
            }
            if (k > 0) minGap = fminf(minGap, prev - best);
            prev = best;
            if (k < TOPK) {
                outw[k] = row[bi];
                outi[k] = (float)bi;
                row[bi] = -CUDART_INF_F;
            }
        }
        if (minGap < FLAG_GAP) {
            int idx = atomicAdd(&g_nflag, 1);
            g_flags[idx] = t;
        }
    }
}

// ============ PASS 2: fp32 recompute for flagged tokens ============
// 1 block/token, 8 warps; warp handles 8 experts; lanes span k (coalesced).
__global__ __launch_bounds__(256)
void fix_kernel(const float* __restrict__ x,
                const float* __restrict__ w,
                const float* __restrict__ bias,
                float* __restrict__ out)
{
    __shared__ float row[NE];

    const int n    = g_nflag;
    const int lane = threadIdx.x & 31;
    const int warp = threadIdx.x >> 5;     // 0..7

    for (int i = blockIdx.x; i < n; i += gridDim.x) {
        const int tok = g_flags[i];
        const float* xt = x + (size_t)tok * DIM;

        #pragma unroll
        for (int j = 0; j < 8; j++) {
            const int e = warp * 8 + j;
            const float* wt = w + (size_t)e * DIM;

            float a = 0.f;
            #pragma unroll
            for (int kk = 0; kk < DIM / 128; kk++) {     // 16 iterations
                int k = kk * 128 + lane * 4;
                float4 xv = *reinterpret_cast<const float4*>(xt + k);
                float4 wv = *reinterpret_cast<const float4*>(wt + k);
                a = fmaf(xv.x, wv.x, a); a = fmaf(xv.y, wv.y, a);
                a = fmaf(xv.z, wv.z, a); a = fmaf(xv.w, wv.w, a);
            }
            #pragma unroll
            for (int off = 16; off > 0; off >>= 1)
                a += __shfl_xor_sync(0xFFFFFFFFu, a, off);
            if (lane == 0) row[e] = a;
        }
        __syncthreads();

        if (threadIdx.x == 0) {
            float m = row[0];
            #pragma unroll
            for (int q = 1; q < NE; q++) m = fmaxf(m, row[q]);
            float ssum = 0.f;
            #pragma unroll
            for (int q = 0; q < NE; q++) { float ex = __expf(row[q] - m); row[q] = ex; ssum += ex; }
            float inv = 1.0f / ssum;
            #pragma unroll
            for (int q = 0; q < NE; q++) row[q] *= inv;

            float* outw = out + (size_t)tok * TOPK;
            float* outi = out + (size_t)TOKENS * TOPK + (size_t)tok * TOPK;
            #pragma unroll
            for (int k = 0; k < TOPK; k++) {
                float best = -CUDART_INF_F; int bi = 0;
                #pragma unroll
                for (int q = 0; q < NE; q++) {
                    float b = row[q] + __ldg(&bias[q]);
                    if (b > best) { best = b; bi = q; }
                }
                outw[k] = row[bi];
                outi[k] = (float)bi;
                row[bi] = -CUDART_INF_F;
            }
        }
        __syncthreads();
    }
}

extern "C" void kernel_launch(void* const* d_in, const int* in_sizes, int n_in,
                              void* d_out, int out_size)
{
    const float* x    = (const float*)d_in[0];
    const float* w    = (const float*)d_in[1];
    const float* bias = (const float*)d_in[2];
    float* out = (float*)d_out;

    void* nflag_ptr = nullptr;
    cudaGetSymbolAddress(&nflag_ptr, g_nflag);
    cudaMemsetAsync(nflag_ptr, 0, sizeof(int));

    cudaFuncSetAttribute(gate_kernel, cudaFuncAttributeMaxDynamicSharedMemorySize, SMEM_BYTES);
    gate_kernel<<<TOKENS / BM, THREADS, SMEM_BYTES>>>(x, w, bias, out);
    fix_kernel<<<256, 256>>>(x, w, bias, out);
}

// round 15
// speedup vs baseline: 1.1194x; 1.1194x over previous
#include <cuda_runtime.h>
#include <cstdint>
#include <math_constants.h>

#define TOKENS   32768
#define DIM      2048
#define NE       64
#define TOPK     6

#define BM       128              // tokens per CTA
#define BKT      32               // K per chunk
#define NCHUNK   (DIM / BKT)      // 64
#define THREADS  256              // 8 warps: 4 across M (32 rows), 2 across N (32 cols)

#define KB2      40               // bf16 row stride (elements): 32 + 8 pad
#define ROWB     (KB2 * 2)        // 80 bytes per row -> ldmatrix conflict-free

#define OFF_AH   0
#define OFF_AM   (BM * ROWB)                       // 10240
#define OFF_WH   (2 * BM * ROWB)                   // 20480
#define OFF_WM   (2 * BM * ROWB + NE * ROWB)       // 25600
#define STAGE_B  (2 * BM * ROWB + 2 * NE * ROWB)   // 30720
#define BIAS_OFF (2 * STAGE_B)
#define SMEM_BYTES (BIAS_OFF + 256)

#define LSTR     66               // epilogue logits row stride (floats)
#define FLAG_GAP 4e-6f            // ~8x above 4-term bf16 score noise (~5e-7)

// ---- flat flagged-token list ----
__device__ int g_nflag;
__device__ int g_flags[TOKENS];

// pack two fp32 -> bf16x2, round-to-nearest
__device__ __forceinline__ uint32_t pack_bf16(float hi, float lo) {
    uint32_t d;
    asm("cvt.rn.bf16x2.f32 %0, %1, %2;" : "=r"(d) : "f"(hi), "f"(lo));
    return d;
}
__device__ __forceinline__ float bf_lo(uint32_t p) { return __uint_as_float(p << 16); }
__device__ __forceinline__ float bf_hi(uint32_t p) { return __uint_as_float(p & 0xFFFF0000u); }

struct Duo { uint2 h, m; };
// 2-way bf16 split of 4 consecutive values: v ~= h + m (residual ~2^-18 rel)
__device__ __forceinline__ Duo split4(float4 v) {
    Duo t;
    t.h.x = pack_bf16(v.y, v.x);
    t.h.y = pack_bf16(v.w, v.z);
    float r0 = v.x - bf_lo(t.h.x), r1 = v.y - bf_hi(t.h.x);
    float r2 = v.z - bf_lo(t.h.y), r3 = v.w - bf_hi(t.h.y);
    t.m.x = pack_bf16(r1, r0);
    t.m.y = pack_bf16(r3, r2);
    return t;
}

// m16n8k16 bf16 mma, f32 accumulate in-place
__device__ __forceinline__ void mma16(float* c, const uint32_t* a, uint32_t b0, uint32_t b1) {
    asm volatile(
        "mma.sync.aligned.m16n8k16.row.col.f32.bf16.bf16.f32 "
        "{%0,%1,%2,%3}, {%4,%5,%6,%7}, {%8,%9}, {%0,%1,%2,%3};"
        : "+f"(c[0]), "+f"(c[1]), "+f"(c[2]), "+f"(c[3])
        : "r"(a[0]), "r"(a[1]), "r"(a[2]), "r"(a[3]), "r"(b0), "r"(b1));
}

// ldmatrix x4: loads 4 8x8 b16 matrices; matrix i rows addressed by lanes 8i..8i+7
__device__ __forceinline__ void ldmx4(uint32_t* r, uint32_t saddr) {
    asm volatile(
        "ldmatrix.sync.aligned.m8n8.x4.shared.b16 {%0,%1,%2,%3}, [%4];"
        : "=r"(r[0]), "=r"(r[1]), "=r"(r[2]), "=r"(r[3]) : "r"(saddr));
}

// ============================ PASS 1: bf16 4-term MMA GEMM + gate ============================
__global__ __launch_bounds__(THREADS, 2)
void gate_kernel(const float* __restrict__ x,
                 const float* __restrict__ w,
                 const float* __restrict__ bias,
                 float* __restrict__ out)
{
    extern __shared__ __align__(16) unsigned char smem[];
    const uint32_t sb = (uint32_t)__cvta_generic_to_shared(smem);
    float* sBias = reinterpret_cast<float*>(smem + BIAS_OFF);
    float* sLog  = reinterpret_cast<float*>(smem);   // epilogue overlay

    const int tid  = threadIdx.x;
    const int lane = tid & 31;
    const int wid  = tid >> 5;
    const int gid  = lane >> 2;
    const int tg   = lane & 3;
    const int m0   = (wid & 3) * 32;
    const int n0   = (wid >> 2) * 32;
    const int block_m = blockIdx.x * BM;

    if (tid < NE) sBias[tid] = bias[tid];

    const float* xg = x + (size_t)block_m * DIM;

    float acc[2][4][4];
    #pragma unroll
    for (int mt = 0; mt < 2; mt++)
        #pragma unroll
        for (int nt = 0; nt < 4; nt++)
            #pragma unroll
            for (int r = 0; r < 4; r++) acc[mt][nt][r] = 0.f;

    float4 xr[4], wr[2];
    int xtok[4], xcq[4], wexp[2], wcq[2];
    #pragma unroll
    for (int i = 0; i < 4; i++) {
        int li = i * THREADS + tid; xtok[i] = li >> 3; xcq[i] = li & 7;
    }
    #pragma unroll
    for (int i = 0; i < 2; i++) {
        int li = i * THREADS + tid; wexp[i] = li >> 3; wcq[i] = li & 7;
    }

    // ---- precomputed ldmatrix lane address offsets (within a stage) ----
    // A: row = m0 + mt*16 + (lane&15); kbyte = q*32 + ((lane>>4)<<4)
    const uint32_t a_lane_off = (uint32_t)((m0 + (lane & 15)) * ROWB + ((lane >> 4) << 4));
    // B: row = n0 + nt2*16 + ((lane>>4)<<3) + (lane&7); kbyte = q*32 + (((lane>>3)&1)<<4)
    const uint32_t b_lane_off = (uint32_t)((n0 + ((lane >> 4) << 3) + (lane & 7)) * ROWB
                                           + (((lane >> 3) & 1) << 4));

    auto ldg_chunk = [&](int c) {
        int k0 = c * BKT;
        #pragma unroll
        for (int i = 0; i < 4; i++)
            xr[i] = *reinterpret_cast<const float4*>(xg + (size_t)xtok[i] * DIM + k0 + xcq[i] * 4);
        #pragma unroll
        for (int i = 0; i < 2; i++)
            wr[i] = *reinterpret_cast<const float4*>(w + (size_t)wexp[i] * DIM + k0 + wcq[i] * 4);
    };
    auto sts_chunk = [&](int s) {
        unsigned char* st = smem + s * STAGE_B;
        #pragma unroll
        for (int i = 0; i < 4; i++) {
            Duo t = split4(xr[i]);
            int off = xtok[i] * ROWB + xcq[i] * 8;
            *reinterpret_cast<uint2*>(st + OFF_AH + off) = t.h;
            *reinterpret_cast<uint2*>(st + OFF_AM + off) = t.m;
        }
        #pragma unroll
        for (int i = 0; i < 2; i++) {
            Duo t = split4(wr[i]);
            int off = wexp[i] * ROWB + wcq[i] * 8;
            *reinterpret_cast<uint2*>(st + OFF_WH + off) = t.h;
            *reinterpret_cast<uint2*>(st + OFF_WM + off) = t.m;
        }
    };

    ldg_chunk(0);
    sts_chunk(0);
    __syncthreads();
    ldg_chunk(1);

    for (int c = 0; c < NCHUNK; c++) {
        const int s = c & 1;
        if (c + 1 < NCHUNK) {
            sts_chunk(s ^ 1);
            if (c + 2 < NCHUNK) ldg_chunk(c + 2);
        }

        const uint32_t stAh = sb + s * STAGE_B + OFF_AH + a_lane_off;
        const uint32_t stAm = sb + s * STAGE_B + OFF_AM + a_lane_off;
        const uint32_t stWh = sb + s * STAGE_B + OFF_WH + b_lane_off;
        const uint32_t stWm = sb + s * STAGE_B + OFF_WM + b_lane_off;

        #pragma unroll
        for (int q = 0; q < BKT / 16; q++) {
            const uint32_t kq = q * 32;

            // ---- A fragments via ldmatrix.x4: regs = {a0,a1,a2,a3} ----
            uint32_t ah[2][4], am[2][4];
            #pragma unroll
            for (int mt = 0; mt < 2; mt++) {
                ldmx4(ah[mt], stAh + mt * (16 * ROWB) + kq);
                ldmx4(am[mt], stAm + mt * (16 * ROWB) + kq);
            }

            // ---- B fragments via ldmatrix.x4: regs = {b0(sub0),b1(sub0),b0(sub1),b1(sub1)} ----
            uint32_t bh[2][4], bm[2][4];
            #pragma unroll
            for (int nt2 = 0; nt2 < 2; nt2++) {
                ldmx4(bh[nt2], stWh + nt2 * (16 * ROWB) + kq);
                ldmx4(bm[nt2], stWm + nt2 * (16 * ROWB) + kq);
            }

            #pragma unroll
            for (int nt2 = 0; nt2 < 2; nt2++)
                #pragma unroll
                for (int sub = 0; sub < 2; sub++) {
                    const int nt = nt2 * 2 + sub;
                    uint32_t bh0 = bh[nt2][sub * 2], bh1 = bh[nt2][sub * 2 + 1];
                    uint32_t bm0 = bm[nt2][sub * 2], bm1 = bm[nt2][sub * 2 + 1];
                    #pragma unroll
                    for (int mt = 0; mt < 2; mt++) {
                        float* cc = acc[mt][nt];
                        mma16(cc, ah[mt], bh0, bh1);   // hi*hi
                        mma16(cc, ah[mt], bm0, bm1);   // hi*mid
                        mma16(cc, am[mt], bh0, bh1);   // mid*hi
                        mma16(cc, am[mt], bm0, bm1);   // mid*mid
                    }
                }
        }
        __syncthreads();
    }

    // ---- dump logits ----
    #pragma unroll
    for (int mt = 0; mt < 2; mt++)
        #pragma unroll
        for (int nt = 0; nt < 4; nt++) {
            int row = m0 + mt * 16 + gid;
            int col = n0 + nt * 8 + tg * 2;
            *reinterpret_cast<float2*>(&sLog[row * LSTR + col]) =
                make_float2(acc[mt][nt][0], acc[mt][nt][1]);
            *reinterpret_cast<float2*>(&sLog[(row + 8) * LSTR + col]) =
                make_float2(acc[mt][nt][2], acc[mt][nt][3]);
        }
    __syncthreads();

    // ---- epilogue: softmax, top-6, ambiguity flag ----
    if (tid < BM) {
        float* row = sLog + tid * LSTR;

        float m = row[0];
        #pragma unroll
        for (int e = 1; e < NE; e++) m = fmaxf(m, row[e]);
        float ssum = 0.f;
        #pragma unroll
        for (int e = 0; e < NE; e++) { float ex = __expf(row[e] - m); row[e] = ex; ssum += ex; }
        float inv = 1.0f / ssum;
        #pragma unroll
        for (int e = 0; e < NE; e++) row[e] *= inv;

        const int t = block_m + tid;
        float* outw = out + (size_t)t * TOPK;
        float* outi = out + (size_t)TOKENS * TOPK + (size_t)t * TOPK;

        float prev = 0.f, minGap = CUDART_INF_F;
        #pragma unroll
        for (int k = 0; k < TOPK + 1; k++) {
            float best = -CUDART_INF_F; int bi = 0;
            #pragma unroll
            for (int e = 0; e < NE; e++) {
                float b = row[e] + sBias[e];
                if (b > best) { best = b; bi = e; }
            }
            if (k > 0) minGap = fminf(minGap, prev - best);
            prev = best;
            if (k < TOPK) {
                outw[k] = row[bi];
                outi[k] = (float)bi;
                row[bi] = -CUDART_INF_F;
            }
        }
        if (minGap < FLAG_GAP) {
            int idx = atomicAdd(&g_nflag, 1);
            g_flags[idx] = t;
        }
    }
}

// ============ PASS 2: fp32 recompute for flagged tokens ============
// 1 block/token, 8 warps; warp handles 8 experts; lanes span k (coalesced).
__global__ __launch_bounds__(256)
void fix_kernel(const float* __restrict__ x,
                const float* __restrict__ w,
                const float* __restrict__ bias,
                float* __restrict__ out)
{
    __shared__ float row[NE];

    const int n    = g_nflag;
    const int lane = threadIdx.x & 31;
    const int warp = threadIdx.x >> 5;     // 0..7

    for (int i = blockIdx.x; i < n; i += gridDim.x) {
        const int tok = g_flags[i];
        const float* xt = x + (size_t)tok * DIM;

        #pragma unroll
        for (int j = 0; j < 8; j++) {
            const int e = warp * 8 + j;
            const float* wt = w + (size_t)e * DIM;

            float a = 0.f;
            #pragma unroll
            for (int kk = 0; kk < DIM / 128; kk++) {     // 16 iterations
                int k = kk * 128 + lane * 4;
                float4 xv = *reinterpret_cast<const float4*>(xt + k);
                float4 wv = *reinterpret_cast<const float4*>(wt + k);
                a = fmaf(xv.x, wv.x, a); a = fmaf(xv.y, wv.y, a);
                a = fmaf(xv.z, wv.z, a); a = fmaf(xv.w, wv.w, a);
            }
            #pragma unroll
            for (int off = 16; off > 0; off >>= 1)
                a += __shfl_xor_sync(0xFFFFFFFFu, a, off);
            if (lane == 0) row[e] = a;
        }
        __syncthreads();

        if (threadIdx.x == 0) {
            float m = row[0];
            #pragma unroll
            for (int q = 1; q < NE; q++) m = fmaxf(m, row[q]);
            float ssum = 0.f;
            #pragma unroll
            for (int q = 0; q < NE; q++) { float ex = __expf(row[q] - m); row[q] = ex; ssum += ex; }
            float inv = 1.0f / ssum;
            #pragma unroll
            for (int q = 0; q < NE; q++) row[q] *= inv;

            float* outw = out + (size_t)tok * TOPK;
            float* outi = out + (size_t)TOKENS * TOPK + (size_t)tok * TOPK;
            #pragma unroll
            for (int k = 0; k < TOPK; k++) {
                float best = -CUDART_INF_F; int bi = 0;
                #pragma unroll
                for (int q = 0; q < NE; q++) {
                    float b = row[q] + __ldg(&bias[q]);
                    if (b > best) { best = b; bi = q; }
                }
                outw[k] = row[bi];
                outi[k] = (float)bi;
                row[bi] = -CUDART_INF_F;
            }
        }
        __syncthreads();
    }
}

extern "C" void kernel_launch(void* const* d_in, const int* in_sizes, int n_in,
                              void* d_out, int out_size)
{
    const float* x    = (const float*)d_in[0];
    const float* w    = (const float*)d_in[1];
    const float* bias = (const float*)d_in[2];
    float* out = (float*)d_out;

    void* nflag_ptr = nullptr;
    cudaGetSymbolAddress(&nflag_ptr, g_nflag);
    cudaMemsetAsync(nflag_ptr, 0, sizeof(int));

    cudaFuncSetAttribute(gate_kernel, cudaFuncAttributeMaxDynamicSharedMemorySize, SMEM_BYTES);
    gate_kernel<<<TOKENS / BM, THREADS, SMEM_BYTES>>>(x, w, bias, out);
    fix_kernel<<<256, 256>>>(x, w, bias, out);
}

// round 16
// speedup vs baseline: 1.2552x; 1.1213x over previous
#include <cuda_runtime.h>
#include <cuda_fp16.h>
#include <cstdint>
#include <math_constants.h>

#define TOKENS   32768
#define DIM      2048
#define NE       64
#define TOPK     6

#define BM       128              // tokens per CTA
#define BKT      32               // K per chunk
#define NCHUNK   (DIM / BKT)      // 64
#define THREADS  256              // 8 warps: 4 across M (32 rows), 2 across N (32 cols)

#define KB2      40               // fp16 row stride (elements): 32 + 8 pad
#define ROWB     (KB2 * 2)        // 80 bytes per row -> ldmatrix conflict-free

#define OFF_AH   0
#define OFF_AM   (BM * ROWB)                       // 10240
#define OFF_WH   (2 * BM * ROWB)                   // 20480
#define OFF_WM   (2 * BM * ROWB + NE * ROWB)       // 25600
#define STAGE_B  (2 * BM * ROWB + 2 * NE * ROWB)   // 30720
#define BIAS_OFF (2 * STAGE_B)
#define SMEM_BYTES (BIAS_OFF + 256)

#define LSTR     66               // epilogue logits row stride (floats)
#define FLAG_GAP 4e-6f            // far above fp16 3-term score noise (~3e-8)

// ---- flat flagged-token list ----
__device__ int g_nflag;
__device__ int g_flags[TOKENS];

struct Duo { uint2 h, m; };
// 2-way fp16 split of 4 consecutive values: v ~= h + m (residual ~2^-23 rel)
__device__ __forceinline__ Duo split4(float4 v) {
    Duo t;
    __half2 h0 = __floats2half2_rn(v.x, v.y);   // .x -> low half
    __half2 h1 = __floats2half2_rn(v.z, v.w);
    float r0 = v.x - __low2float(h0), r1 = v.y - __high2float(h0);
    float r2 = v.z - __low2float(h1), r3 = v.w - __high2float(h1);
    __half2 m0 = __floats2half2_rn(r0, r1);
    __half2 m1 = __floats2half2_rn(r2, r3);
    t.h.x = *reinterpret_cast<uint32_t*>(&h0);
    t.h.y = *reinterpret_cast<uint32_t*>(&h1);
    t.m.x = *reinterpret_cast<uint32_t*>(&m0);
    t.m.y = *reinterpret_cast<uint32_t*>(&m1);
    return t;
}

// m16n8k16 fp16 mma, f32 accumulate in-place
__device__ __forceinline__ void mma16(float* c, const uint32_t* a, uint32_t b0, uint32_t b1) {
    asm volatile(
        "mma.sync.aligned.m16n8k16.row.col.f32.f16.f16.f32 "
        "{%0,%1,%2,%3}, {%4,%5,%6,%7}, {%8,%9}, {%0,%1,%2,%3};"
        : "+f"(c[0]), "+f"(c[1]), "+f"(c[2]), "+f"(c[3])
        : "r"(a[0]), "r"(a[1]), "r"(a[2]), "r"(a[3]), "r"(b0), "r"(b1));
}

// ldmatrix x4: loads 4 8x8 b16 matrices; matrix i rows addressed by lanes 8i..8i+7
__device__ __forceinline__ void ldmx4(uint32_t* r, uint32_t saddr) {
    asm volatile(
        "ldmatrix.sync.aligned.m8n8.x4.shared.b16 {%0,%1,%2,%3}, [%4];"
        : "=r"(r[0]), "=r"(r[1]), "=r"(r[2]), "=r"(r[3]) : "r"(saddr));
}

// ============================ PASS 1: fp16 3-term MMA GEMM + gate ============================
__global__ __launch_bounds__(THREADS, 2)
void gate_kernel(const float* __restrict__ x,
                 const float* __restrict__ w,
                 const float* __restrict__ bias,
                 float* __restrict__ out)
{
    extern __shared__ __align__(16) unsigned char smem[];
    const uint32_t sb = (uint32_t)__cvta_generic_to_shared(smem);
    float* sBias = reinterpret_cast<float*>(smem + BIAS_OFF);
    float* sLog  = reinterpret_cast<float*>(smem);   // epilogue overlay

    const int tid  = threadIdx.x;
    const int lane = tid & 31;
    const int wid  = tid >> 5;
    const int gid  = lane >> 2;
    const int tg   = lane & 3;
    const int m0   = (wid & 3) * 32;
    const int n0   = (wid >> 2) * 32;
    const int block_m = blockIdx.x * BM;

    if (tid < NE) sBias[tid] = bias[tid];

    const float* xg = x + (size_t)block_m * DIM;

    float acc[2][4][4];
    #pragma unroll
    for (int mt = 0; mt < 2; mt++)
        #pragma unroll
        for (int nt = 0; nt < 4; nt++)
            #pragma unroll
            for (int r = 0; r < 4; r++) acc[mt][nt][r] = 0.f;

    float4 xr[4], wr[2];
    int xtok[4], xcq[4], wexp[2], wcq[2];
    #pragma unroll
    for (int i = 0; i < 4; i++) {
        int li = i * THREADS + tid; xtok[i] = li >> 3; xcq[i] = li & 7;
    }
    #pragma unroll
    for (int i = 0; i < 2; i++) {
        int li = i * THREADS + tid; wexp[i] = li >> 3; wcq[i] = li & 7;
    }

    // ---- precomputed ldmatrix lane address offsets (within a stage) ----
    const uint32_t a_lane_off = (uint32_t)((m0 + (lane & 15)) * ROWB + ((lane >> 4) << 4));
    const uint32_t b_lane_off = (uint32_t)((n0 + ((lane >> 4) << 3) + (lane & 7)) * ROWB
                                           + (((lane >> 3) & 1) << 4));

    auto ldg_chunk = [&](int c) {
        int k0 = c * BKT;
        #pragma unroll
        for (int i = 0; i < 4; i++)
            xr[i] = *reinterpret_cast<const float4*>(xg + (size_t)xtok[i] * DIM + k0 + xcq[i] * 4);
        #pragma unroll
        for (int i = 0; i < 2; i++)
            wr[i] = *reinterpret_cast<const float4*>(w + (size_t)wexp[i] * DIM + k0 + wcq[i] * 4);
    };
    auto sts_chunk = [&](int s) {
        unsigned char* st = smem + s * STAGE_B;
        #pragma unroll
        for (int i = 0; i < 4; i++) {
            Duo t = split4(xr[i]);
            int off = xtok[i] * ROWB + xcq[i] * 8;
            *reinterpret_cast<uint2*>(st + OFF_AH + off) = t.h;
            *reinterpret_cast<uint2*>(st + OFF_AM + off) = t.m;
        }
        #pragma unroll
        for (int i = 0; i < 2; i++) {
            Duo t = split4(wr[i]);
            int off = wexp[i] * ROWB + wcq[i] * 8;
            *reinterpret_cast<uint2*>(st + OFF_WH + off) = t.h;
            *reinterpret_cast<uint2*>(st + OFF_WM + off) = t.m;
        }
    };

    ldg_chunk(0);
    sts_chunk(0);
    __syncthreads();
    ldg_chunk(1);

    for (int c = 0; c < NCHUNK; c++) {
        const int s = c & 1;
        if (c + 1 < NCHUNK) {
            sts_chunk(s ^ 1);
            if (c + 2 < NCHUNK) ldg_chunk(c + 2);
        }

        const uint32_t stAh = sb + s * STAGE_B + OFF_AH + a_lane_off;
        const uint32_t stAm = sb + s * STAGE_B + OFF_AM + a_lane_off;
        const uint32_t stWh = sb + s * STAGE_B + OFF_WH + b_lane_off;
        const uint32_t stWm = sb + s * STAGE_B + OFF_WM + b_lane_off;

        #pragma unroll
        for (int q = 0; q < BKT / 16; q++) {
            const uint32_t kq = q * 32;

            uint32_t ah[2][4], am[2][4];
            #pragma unroll
            for (int mt = 0; mt < 2; mt++) {
                ldmx4(ah[mt], stAh + mt * (16 * ROWB) + kq);
                ldmx4(am[mt], stAm + mt * (16 * ROWB) + kq);
            }

            uint32_t bh[2][4], bm[2][4];
            #pragma unroll
            for (int nt2 = 0; nt2 < 2; nt2++) {
                ldmx4(bh[nt2], stWh + nt2 * (16 * ROWB) + kq);
                ldmx4(bm[nt2], stWm + nt2 * (16 * ROWB) + kq);
            }

            #pragma unroll
            for (int nt2 = 0; nt2 < 2; nt2++)
                #pragma unroll
                for (int sub = 0; sub < 2; sub++) {
                    const int nt = nt2 * 2 + sub;
                    uint32_t bh0 = bh[nt2][sub * 2], bh1 = bh[nt2][sub * 2 + 1];
                    uint32_t bm0 = bm[nt2][sub * 2], bm1 = bm[nt2][sub * 2 + 1];
                    #pragma unroll
                    for (int mt = 0; mt < 2; mt++) {
                        float* cc = acc[mt][nt];
                        mma16(cc, ah[mt], bh0, bh1);   // hi*hi
                        mma16(cc, ah[mt], bm0, bm1);   // hi*mid
                        mma16(cc, am[mt], bh0, bh1);   // mid*hi
                    }
                }
        }
        __syncthreads();
    }

    // ---- dump logits ----
    #pragma unroll
    for (int mt = 0; mt < 2; mt++)
        #pragma unroll
        for (int nt = 0; nt < 4; nt++) {
            int row = m0 + mt * 16 + gid;
            int col = n0 + nt * 8 + tg * 2;
            *reinterpret_cast<float2*>(&sLog[row * LSTR + col]) =
                make_float2(acc[mt][nt][0], acc[mt][nt][1]);
            *reinterpret_cast<float2*>(&sLog[(row + 8) * LSTR + col]) =
                make_float2(acc[mt][nt][2], acc[mt][nt][3]);
        }
    __syncthreads();

    // ---- epilogue: softmax, top-6, ambiguity flag ----
    if (tid < BM) {
        float* row = sLog + tid * LSTR;

        float m = row[0];
        #pragma unroll
        for (int e = 1; e < NE; e++) m = fmaxf(m, row[e]);
        float ssum = 0.f;
        #pragma unroll
        for (int e = 0; e < NE; e++) { float ex = __expf(row[e] - m); row[e] = ex; ssum += ex; }
        float inv = 1.0f / ssum;
        #pragma unroll
        for (int e = 0; e < NE; e++) row[e] *= inv;

        const int t = block_m + tid;
        float* outw = out + (size_t)t * TOPK;
        float* outi = out + (size_t)TOKENS * TOPK + (size_t)t * TOPK;

        float prev = 0.f, minGap = CUDART_INF_F;
        #pragma unroll
        for (int k = 0; k < TOPK + 1; k++) {
            float best = -CUDART_INF_F; int bi = 0;
            #pragma unroll
            for (int e = 0; e < NE; e++) {
                float b = row[e] + sBias[e];
                if (b > best) { best = b; bi = e; }
            }
            if (k > 0) minGap = fminf(minGap, prev - best);
            prev = best;
            if (k < TOPK) {
                outw[k] = row[bi];
                outi[k] = (float)bi;
                row[bi] = -CUDART_INF_F;
            }
        }
        if (minGap < FLAG_GAP) {
            int idx = atomicAdd(&g_nflag, 1);
            g_flags[idx] = t;
        }
    }
}

// ============ PASS 2: fp32 recompute for flagged tokens ============
__global__ __launch_bounds__(256)
void fix_kernel(const float* __restrict__ x,
                const float* __restrict__ w,
                const float* __restrict__ bias,
                float* __restrict__ out)
{
    __shared__ float row[NE];

    const int n    = g_nflag;
    const int lane = threadIdx.x & 31;
    const int warp = threadIdx.x >> 5;     // 0..7

    for (int i = blockIdx.x; i < n; i += gridDim.x) {
        const int tok = g_flags[i];
        const float* xt = x + (size_t)tok * DIM;

        #pragma unroll
        for (int j = 0; j < 8; j++) {
            const int e = warp * 8 + j;
            const float* wt = w + (size_t)e * DIM;

            float a = 0.f;
            #pragma unroll
            for (int kk = 0; kk < DIM / 128; kk++) {
                int k = kk * 128 + lane * 4;
                float4 xv = *reinterpret_cast<const float4*>(xt + k);
                float4 wv = *reinterpret_cast<const float4*>(wt + k);
                a = fmaf(xv.x, wv.x, a); a = fmaf(xv.y, wv.y, a);
                a = fmaf(xv.z, wv.z, a); a = fmaf(xv.w, wv.w, a);
            }
            #pragma unroll
            for (int off = 16; off > 0; off >>= 1)
                a += __shfl_xor_sync(0xFFFFFFFFu, a, off);
            if (lane == 0) row[e] = a;
        }
        __syncthreads();

        if (threadIdx.x == 0) {
            float m = row[0];
            #pragma unroll
            for (int q = 1; q < NE; q++) m = fmaxf(m, row[q]);
            float ssum = 0.f;
            #pragma unroll
            for (int q = 0; q < NE; q++) { float ex = __expf(row[q] - m); row[q] = ex; ssum += ex; }
            float inv = 1.0f / ssum;
            #pragma unroll
            for (int q = 0; q < NE; q++) row[q] *= inv;

            float* outw = out + (size_t)tok * TOPK;
            float* outi = out + (size_t)TOKENS * TOPK + (size_t)tok * TOPK;
            #pragma unroll
            for (int k = 0; k < TOPK; k++) {
                float best = -CUDART_INF_F; int bi = 0;
                #pragma unroll
                for (int q = 0; q < NE; q++) {
                    float b = row[q] + __ldg(&bias[q]);
                    if (b > best) { best = b; bi = q; }
                }
                outw[k] = row[bi];
                outi[k] = (float)bi;
                row[bi] = -CUDART_INF_F;
            }
        }
        __syncthreads();
    }
}

extern "C" void kernel_launch(void* const* d_in, const int* in_sizes, int n_in,
                              void* d_out, int out_size)
{
    const float* x    = (const float*)d_in[0];
    const float* w    = (const float*)d_in[1];
    const float* bias = (const float*)d_in[2];
    float* out = (float*)d_out;

    void* nflag_ptr = nullptr;
    cudaGetSymbolAddress(&nflag_ptr, g_nflag);
    cudaMemsetAsync(nflag_ptr, 0, sizeof(int));

    cudaFuncSetAttribute(gate_kernel, cudaFuncAttributeMaxDynamicSharedMemorySize, SMEM_BYTES);
    gate_kernel<<<TOKENS / BM, THREADS, SMEM_BYTES>>>(x, w, bias, out);
    fix_kernel<<<256, 256>>>(x, w, bias, out);
}

// round 17
// speedup vs baseline: 1.2951x; 1.0318x over previous
#include <cuda_runtime.h>
#include <cuda_fp16.h>
#include <cstdint>
#include <math_constants.h>

#define TOKENS   32768
#define DIM      2048
#define NE       64
#define TOPK     6

#define BM       128              // tokens per CTA
#define BKT      32               // K per chunk
#define NCHUNK   (DIM / BKT)      // 64
#define THREADS  256              // 8 warps: 4 across M (32 rows), 2 across N (32 cols)

#define KB2      40               // fp16 row stride (elements): 32 + 8 pad
#define ROWB     (KB2 * 2)        // 80 bytes per row -> ldmatrix conflict-free

#define OFF_AH   0
#define OFF_AM   (BM * ROWB)                       // 10240
#define OFF_WH   (2 * BM * ROWB)                   // 20480
#define OFF_WM   (2 * BM * ROWB + NE * ROWB)       // 25600
#define STAGE_B  (2 * BM * ROWB + 2 * NE * ROWB)   // 30720
#define BIAS_OFF (2 * STAGE_B)
#define SMEM_BYTES (BIAS_OFF + 256)

#define LSTR     66               // epilogue logits row stride (floats)
#define FLAG_GAP 4e-6f            // far above fp16 3-term score noise (~3e-8)

// ---- flat flagged-token list + pre-split W (static device globals) ----
__device__ int g_nflag;
__device__ int g_flags[TOKENS];
__device__ uint2 g_wh[NE * DIM / 4];   // fp16 hi components, 4 per uint2
__device__ uint2 g_wm[NE * DIM / 4];   // fp16 mid components

struct Duo { uint2 h, m; };
// 2-way fp16 split of 4 consecutive values: v ~= h + m (residual ~2^-23 rel)
__device__ __forceinline__ Duo split4(float4 v) {
    Duo t;
    __half2 h0 = __floats2half2_rn(v.x, v.y);   // .x -> low half
    __half2 h1 = __floats2half2_rn(v.z, v.w);
    float r0 = v.x - __low2float(h0), r1 = v.y - __high2float(h0);
    float r2 = v.z - __low2float(h1), r3 = v.w - __high2float(h1);
    __half2 m0 = __floats2half2_rn(r0, r1);
    __half2 m1 = __floats2half2_rn(r2, r3);
    t.h.x = *reinterpret_cast<uint32_t*>(&h0);
    t.h.y = *reinterpret_cast<uint32_t*>(&h1);
    t.m.x = *reinterpret_cast<uint32_t*>(&m0);
    t.m.y = *reinterpret_cast<uint32_t*>(&m1);
    return t;
}

// ---- one-shot W pre-split: fp32 W -> (g_wh, g_wm) fp16 pairs ----
__global__ __launch_bounds__(256)
void wsplit_kernel(const float* __restrict__ w) {
    int idx = blockIdx.x * 256 + threadIdx.x;          // one float4 per thread
    float4 v = *reinterpret_cast<const float4*>(w + idx * 4);
    Duo t = split4(v);
    g_wh[idx] = t.h;
    g_wm[idx] = t.m;
}

// m16n8k16 fp16 mma, f32 accumulate in-place
__device__ __forceinline__ void mma16(float* c, const uint32_t* a, uint32_t b0, uint32_t b1) {
    asm volatile(
        "mma.sync.aligned.m16n8k16.row.col.f32.f16.f16.f32 "
        "{%0,%1,%2,%3}, {%4,%5,%6,%7}, {%8,%9}, {%0,%1,%2,%3};"
        : "+f"(c[0]), "+f"(c[1]), "+f"(c[2]), "+f"(c[3])
        : "r"(a[0]), "r"(a[1]), "r"(a[2]), "r"(a[3]), "r"(b0), "r"(b1));
}

// ldmatrix x4: loads 4 8x8 b16 matrices; matrix i rows addressed by lanes 8i..8i+7
__device__ __forceinline__ void ldmx4(uint32_t* r, uint32_t saddr) {
    asm volatile(
        "ldmatrix.sync.aligned.m8n8.x4.shared.b16 {%0,%1,%2,%3}, [%4];"
        : "=r"(r[0]), "=r"(r[1]), "=r"(r[2]), "=r"(r[3]) : "r"(saddr));
}

// ============================ PASS 1: fp16 3-term MMA GEMM + gate ============================
__global__ __launch_bounds__(THREADS, 2)
void gate_kernel(const float* __restrict__ x,
                 const float* __restrict__ bias,
                 float* __restrict__ out)
{
    extern __shared__ __align__(16) unsigned char smem[];
    const uint32_t sb = (uint32_t)__cvta_generic_to_shared(smem);
    float* sBias = reinterpret_cast<float*>(smem + BIAS_OFF);
    float* sLog  = reinterpret_cast<float*>(smem);   // epilogue overlay

    const int tid  = threadIdx.x;
    const int lane = tid & 31;
    const int wid  = tid >> 5;
    const int gid  = lane >> 2;
    const int tg   = lane & 3;
    const int m0   = (wid & 3) * 32;
    const int n0   = (wid >> 2) * 32;
    const int block_m = blockIdx.x * BM;

    if (tid < NE) sBias[tid] = bias[tid];

    const float* xg = x + (size_t)block_m * DIM;

    float acc[2][4][4];
    #pragma unroll
    for (int mt = 0; mt < 2; mt++)
        #pragma unroll
        for (int nt = 0; nt < 4; nt++)
            #pragma unroll
            for (int r = 0; r < 4; r++) acc[mt][nt][r] = 0.f;

    // x LDG tiling: 4 float4/thread per chunk
    float4 xr[4];
    int xtok[4], xcq[4];
    #pragma unroll
    for (int i = 0; i < 4; i++) {
        int li = i * THREADS + tid; xtok[i] = li >> 3; xcq[i] = li & 7;
    }
    // W LDG tiling: pre-split fp16; thread covers expert=tid>>2, quad=tid&3 (8 halves each)
    const int wexp = tid >> 2, wq = tid & 3;
    uint4 whr, wmr;

    // ---- precomputed ldmatrix lane address offsets (within a stage) ----
    const uint32_t a_lane_off = (uint32_t)((m0 + (lane & 15)) * ROWB + ((lane >> 4) << 4));
    const uint32_t b_lane_off = (uint32_t)((n0 + ((lane >> 4) << 3) + (lane & 7)) * ROWB
                                           + (((lane >> 3) & 1) << 4));

    auto ldg_chunk = [&](int c) {
        int k0 = c * BKT;
        #pragma unroll
        for (int i = 0; i < 4; i++)
            xr[i] = *reinterpret_cast<const float4*>(xg + (size_t)xtok[i] * DIM + k0 + xcq[i] * 4);
        int wi = wexp * (DIM / 4) + k0 / 4 + wq * 2;   // uint2 index, even -> uint4 aligned
        whr = *reinterpret_cast<const uint4*>(g_wh + wi);
        wmr = *reinterpret_cast<const uint4*>(g_wm + wi);
    };
    auto sts_chunk = [&](int s) {
        unsigned char* st = smem + s * STAGE_B;
        #pragma unroll
        for (int i = 0; i < 4; i++) {
            Duo t = split4(xr[i]);
            int off = xtok[i] * ROWB + xcq[i] * 8;
            *reinterpret_cast<uint2*>(st + OFF_AH + off) = t.h;
            *reinterpret_cast<uint2*>(st + OFF_AM + off) = t.m;
        }
        int woff = wexp * ROWB + wq * 16;
        *reinterpret_cast<uint4*>(st + OFF_WH + woff) = whr;
        *reinterpret_cast<uint4*>(st + OFF_WM + woff) = wmr;
    };

    ldg_chunk(0);
    sts_chunk(0);
    __syncthreads();
    ldg_chunk(1);

    for (int c = 0; c < NCHUNK; c++) {
        const int s = c & 1;
        if (c + 1 < NCHUNK) {
            sts_chunk(s ^ 1);
            if (c + 2 < NCHUNK) ldg_chunk(c + 2);
        }

        const uint32_t stAh = sb + s * STAGE_B + OFF_AH + a_lane_off;
        const uint32_t stAm = sb + s * STAGE_B + OFF_AM + a_lane_off;
        const uint32_t stWh = sb + s * STAGE_B + OFF_WH + b_lane_off;
        const uint32_t stWm = sb + s * STAGE_B + OFF_WM + b_lane_off;

        #pragma unroll
        for (int q = 0; q < BKT / 16; q++) {
            const uint32_t kq = q * 32;

            uint32_t ah[2][4], am[2][4];
            #pragma unroll
            for (int mt = 0; mt < 2; mt++) {
                ldmx4(ah[mt], stAh + mt * (16 * ROWB) + kq);
                ldmx4(am[mt], stAm + mt * (16 * ROWB) + kq);
            }

            uint32_t bh[2][4], bm[2][4];
            #pragma unroll
            for (int nt2 = 0; nt2 < 2; nt2++) {
                ldmx4(bh[nt2], stWh + nt2 * (16 * ROWB) + kq);
                ldmx4(bm[nt2], stWm + nt2 * (16 * ROWB) + kq);
            }

            // term-major ordering: each accumulator touched 3x, far apart
            #pragma unroll
            for (int nt2 = 0; nt2 < 2; nt2++)
                #pragma unroll
                for (int sub = 0; sub < 2; sub++)
                    #pragma unroll
                    for (int mt = 0; mt < 2; mt++)
                        mma16(acc[mt][nt2 * 2 + sub], ah[mt],
                              bh[nt2][sub * 2], bh[nt2][sub * 2 + 1]);   // hi*hi
            #pragma unroll
            for (int nt2 = 0; nt2 < 2; nt2++)
                #pragma unroll
                for (int sub = 0; sub < 2; sub++)
                    #pragma unroll
                    for (int mt = 0; mt < 2; mt++)
                        mma16(acc[mt][nt2 * 2 + sub], ah[mt],
                              bm[nt2][sub * 2], bm[nt2][sub * 2 + 1]);   // hi*mid
            #pragma unroll
            for (int nt2 = 0; nt2 < 2; nt2++)
                #pragma unroll
                for (int sub = 0; sub < 2; sub++)
                    #pragma unroll
                    for (int mt = 0; mt < 2; mt++)
                        mma16(acc[mt][nt2 * 2 + sub], am[mt],
                              bh[nt2][sub * 2], bh[nt2][sub * 2 + 1]);   // mid*hi
        }
        __syncthreads();
    }

    // ---- dump logits ----
    #pragma unroll
    for (int mt = 0; mt < 2; mt++)
        #pragma unroll
        for (int nt = 0; nt < 4; nt++) {
            int row = m0 + mt * 16 + gid;
            int col = n0 + nt * 8 + tg * 2;
            *reinterpret_cast<float2*>(&sLog[row * LSTR + col]) =
                make_float2(acc[mt][nt][0], acc[mt][nt][1]);
            *reinterpret_cast<float2*>(&sLog[(row + 8) * LSTR + col]) =
                make_float2(acc[mt][nt][2], acc[mt][nt][3]);
        }
    __syncthreads();

    // ---- epilogue: softmax, top-6, ambiguity flag ----
    if (tid < BM) {
        float* row = sLog + tid * LSTR;

        float m = row[0];
        #pragma unroll
        for (int e = 1; e < NE; e++) m = fmaxf(m, row[e]);
        float ssum = 0.f;
        #pragma unroll
        for (int e = 0; e < NE; e++) { float ex = __expf(row[e] - m); row[e] = ex; ssum += ex; }
        float inv = 1.0f / ssum;
        #pragma unroll
        for (int e = 0; e < NE; e++) row[e] *= inv;

        const int t = block_m + tid;
        float* outw = out + (size_t)t * TOPK;
        float* outi = out + (size_t)TOKENS * TOPK + (size_t)t * TOPK;

        float prev = 0.f, minGap = CUDART_INF_F;
        #pragma unroll
        for (int k = 0; k < TOPK + 1; k++) {
            float best = -CUDART_INF_F; int bi = 0;
            #pragma unroll
            for (int e = 0; e < NE; e++) {
                float b = row[e] + sBias[e];
                if (b > best) { best = b; bi = e; }
            }
            if (k > 0) minGap = fminf(minGap, prev - best);
            prev = best;
            if (k < TOPK) {
                outw[k] = row[bi];
                outi[k] = (float)bi;
                row[bi] = -CUDART_INF_F;
            }
        }
        if (minGap < FLAG_GAP) {
            int idx = atomicAdd(&g_nflag, 1);
            g_flags[idx] = t;
        }
    }
}

// ============ PASS 2: fp32 recompute for flagged tokens ============
__global__ __launch_bounds__(256)
void fix_kernel(const float* __restrict__ x,
                const float* __restrict__ w,
                const float* __restrict__ bias,
                float* __restrict__ out)
{
    __shared__ float row[NE];

    const int n    = g_nflag;
    const int lane = threadIdx.x & 31;
    const int warp = threadIdx.x >> 5;     // 0..7

    for (int i = blockIdx.x; i < n; i += gridDim.x) {
        const int tok = g_flags[i];
        const float* xt = x + (size_t)tok * DIM;

        #pragma unroll
        for (int j = 0; j < 8; j++) {
            const int e = warp * 8 + j;
            const float* wt = w + (size_t)e * DIM;

            float a = 0.f;
            #pragma unroll
            for (int kk = 0; kk < DIM / 128; kk++) {
                int k = kk * 128 + lane * 4;
                float4 xv = *reinterpret_cast<const float4*>(xt + k);
                float4 wv = *reinterpret_cast<const float4*>(wt + k);
                a = fmaf(xv.x, wv.x, a); a = fmaf(xv.y, wv.y, a);
                a = fmaf(xv.z, wv.z, a); a = fmaf(xv.w, wv.w, a);
            }
            #pragma unroll
            for (int off = 16; off > 0; off >>= 1)
                a += __shfl_xor_sync(0xFFFFFFFFu, a, off);
            if (lane == 0) row[e] = a;
        }
        __syncthreads();

        if (threadIdx.x == 0) {
            float m = row[0];
            #pragma unroll
            for (int q = 1; q < NE; q++) m = fmaxf(m, row[q]);
            float ssum = 0.f;
            #pragma unroll
            for (int q = 0; q < NE; q++) { float ex = __expf(row[q] - m); row[q] = ex; ssum += ex; }
            float inv = 1.0f / ssum;
            #pragma unroll
            for (int q = 0; q < NE; q++) row[q] *= inv;

            float* outw = out + (size_t)tok * TOPK;
            float* outi = out + (size_t)TOKENS * TOPK + (size_t)tok * TOPK;
            #pragma unroll
            for (int k = 0; k < TOPK; k++) {
                float best = -CUDART_INF_F; int bi = 0;
                #pragma unroll
                for (int q = 0; q < NE; q++) {
                    float b = row[q] + __ldg(&bias[q]);
                    if (b > best) { best = b; bi = q; }
                }
                outw[k] = row[bi];
                outi[k] = (float)bi;
                row[bi] = -CUDART_INF_F;
            }
        }
        __syncthreads();
    }
}

extern "C" void kernel_launch(void* const* d_in, const int* in_sizes, int n_in,
                              void* d_out, int out_size)
{
    const float* x    = (const float*)d_in[0];
    const float* w    = (const float*)d_in[1];
    const float* bias = (const float*)d_in[2];
    float* out = (float*)d_out;

    void* nflag_ptr = nullptr;
    cudaGetSymbolAddress(&nflag_ptr, g_nflag);
    cudaMemsetAsync(nflag_ptr, 0, sizeof(int));

    wsplit_kernel<<<NE * DIM / 4 / 256, 256>>>(w);

    cudaFuncSetAttribute(gate_kernel, cudaFuncAttributeMaxDynamicSharedMemorySize, SMEM_BYTES);
    gate_kernel<<<TOKENS / BM, THREADS, SMEM_BYTES>>>(x, bias, out);
    fix_kernel<<<256, 256>>>(x, w, bias, out);
}